// round 10
// baseline (speedup 1.0000x reference)
#include <cuda_runtime.h>
#include <cstdint>

#define LEAK   0.1f
#define BN_EPS 1e-5f

// problem dims
#define B_   16
#define CH   32
#define H0c  48
#define H2c  46
#define H3c  44
#define D0   2304
#define D1   2116
#define D2   1936
#define NF   512
#define BI   512
#define OC   1024
#define BOC  16384
#define NN2  (NF * NF)
#define OSL  (512 * D2)

// padded K strides (multiples of 32)
#define KP0  2304
#define KP1  2144
#define KP2  1952

// ---------------- fp32 scratch ----------------
__device__ float g_S[3 * NN2];          // 0: S0(VQ0), 1: DOT1, 2: S1(VQ1)
__device__ float g_G[9 * NN2];
__device__ float g_OutP[2 * OSL];
__device__ float g_A[BI * NF];
__device__ int   g_cnt[B_ * CH * NF];
__device__ int   g_idx2[BOC];
__device__ int   g_pair[NF * CH];
__device__ float g_qw1[CH * 9];
__device__ float g_qw2[CH * 9];
__device__ float g_qpw1[OC];
__device__ float g_qpw2[OC];
__device__ float g_nfdw[NF];
__device__ float g_nfpw[NF];
__device__ float g_nfdw2[NF];
__device__ float g_nfpw2[NF];

// ---------------- tf32 2-way split arrays (hi plane, lo plane) ----------------
__device__ float g_x2[2L * BI * KP0];
__device__ float g_fdw2s[2L * NF * KP0];
__device__ float g_fpw2s[2L * NF * KP1];
__device__ float g_fdw22s[2L * NF * KP1];
__device__ float g_fpw22s[2L * NF * KP2];
__device__ float g_Cs2[2L * 9 * NF * KP2];
__device__ float g_h12[2L * BI * KP1];

// ---------------- packed fp32x2 helpers (scalar out-GEMM) ----------------
#define FMA2(acc, a, b) asm("fma.rn.f32x2 %0, %1, %2, %0;" : "+l"(acc) : "l"(a), "l"(b))
#define DUP2(d, x) asm("mov.b64 %0, {%1, %1};" : "=l"(d) : "r"(__float_as_uint(x)))

// ---------------- tf32 split helper ----------------
__device__ __forceinline__ void split2(float v, float& hi, float& lo) {
    uint32_t hb; asm("cvt.rna.tf32.f32 %0, %1;" : "=r"(hb) : "f"(v));
    hi = __uint_as_float(hb);
    float r = v - hi;
    uint32_t lb; asm("cvt.rna.tf32.f32 %0, %1;" : "=r"(lb) : "f"(r));
    lo = __uint_as_float(lb);
}

// ================= tf32 mma GEMM core: C[512x512] = A(512xKp) * B(512xKp)^T, 3xTF32 =======
// block 128x128, 256 threads (8 warps = 4m x 2n), warp tile 32x64 (2 m16 x 8 n8 frags)
#define MM_WORDS_HALF 4608            // 128*36 words per buffer
#define MM_SMEM_BYTES (4 * (2 * MM_WORDS_HALF * 2))   // A(2 buf) + B(2 buf) = 73728 B
__device__ __forceinline__ void mm_core(const float* __restrict__ A2, long Asp,
                                        const float* __restrict__ B2, long Bsp,
                                        float* __restrict__ C, int Kp) {
    extern __shared__ float smf[];
    float* AsB = smf;                       // [2][128][36]
    float* BsB = smf + 2 * MM_WORDS_HALF;   // [2][128][36]

    int tid = threadIdx.x;
    int m0 = blockIdx.y * 128, n0 = blockIdx.x * 128;
    int lrow = tid >> 1, lk = (tid & 1) * 16;
    int wid = tid >> 5, lane = tid & 31;
    int wm = (wid & 3) * 32, wn = (wid >> 2) * 64;
    int g = lane >> 2, t4 = lane & 3;

    int nch = Kp >> 5;
    int total = 3 * nch;

    float acc[2][8][4] = {};

    // prologue: chunk 0 (pass 0 = hi*hi)
    {
        const float* Ap = A2 + (long)(m0 + lrow) * Kp + lk;
        const float* Bp = B2 + (long)(n0 + lrow) * Kp + lk;
#pragma unroll
        for (int j = 0; j < 4; j++) {
            float4 va = *(const float4*)(Ap + j * 4);
            float4 vb = *(const float4*)(Bp + j * 4);
            *(float4*)(AsB + lrow * 36 + lk + j * 4) = va;
            *(float4*)(BsB + lrow * 36 + lk + j * 4) = vb;
        }
    }
    __syncthreads();

    int buf = 0;
    for (int c = 0; c < total; c++) {
        bool nxt = (c + 1) < total;
        float4 na[4], nb[4];
        if (nxt) {
            int c2 = c + 1;
            int p = c2 / nch, kb = (c2 - p * nch) * 32;
            const float* Ap = A2 + (p == 2 ? Asp : 0) + (long)(m0 + lrow) * Kp + kb + lk;
            const float* Bp = B2 + (p == 1 ? Bsp : 0) + (long)(n0 + lrow) * Kp + kb + lk;
#pragma unroll
            for (int j = 0; j < 4; j++) {
                na[j] = *(const float4*)(Ap + j * 4);
                nb[j] = *(const float4*)(Bp + j * 4);
            }
        }
        const float* As = AsB + buf * MM_WORDS_HALF;
        const float* Bs = BsB + buf * MM_WORDS_HALF;
#pragma unroll
        for (int kk = 0; kk < 32; kk += 8) {
            uint32_t af[2][4];
#pragma unroll
            for (int mt = 0; mt < 2; mt++) {
                int mb = wm + mt * 16;
                af[mt][0] = __float_as_uint(As[(mb + g) * 36 + kk + t4]);
                af[mt][1] = __float_as_uint(As[(mb + g + 8) * 36 + kk + t4]);
                af[mt][2] = __float_as_uint(As[(mb + g) * 36 + kk + t4 + 4]);
                af[mt][3] = __float_as_uint(As[(mb + g + 8) * 36 + kk + t4 + 4]);
            }
#pragma unroll
            for (int nt = 0; nt < 8; nt++) {
                int nb_ = wn + nt * 8 + g;
                uint32_t b0 = __float_as_uint(Bs[nb_ * 36 + kk + t4]);
                uint32_t b1 = __float_as_uint(Bs[nb_ * 36 + kk + t4 + 4]);
#pragma unroll
                for (int mt = 0; mt < 2; mt++) {
                    asm volatile(
                        "mma.sync.aligned.m16n8k8.row.col.f32.tf32.tf32.f32 "
                        "{%0,%1,%2,%3}, {%4,%5,%6,%7}, {%8,%9}, {%0,%1,%2,%3};"
                        : "+f"(acc[mt][nt][0]), "+f"(acc[mt][nt][1]),
                          "+f"(acc[mt][nt][2]), "+f"(acc[mt][nt][3])
                        : "r"(af[mt][0]), "r"(af[mt][1]), "r"(af[mt][2]), "r"(af[mt][3]),
                          "r"(b0), "r"(b1));
                }
            }
        }
        if (nxt) {
            int bN = buf ^ 1;
#pragma unroll
            for (int j = 0; j < 4; j++) {
                *(float4*)(AsB + bN * MM_WORDS_HALF + lrow * 36 + lk + j * 4) = na[j];
                *(float4*)(BsB + bN * MM_WORDS_HALF + lrow * 36 + lk + j * 4) = nb[j];
            }
            __syncthreads();
            buf = bN;
        }
    }

    // epilogue
#pragma unroll
    for (int mt = 0; mt < 2; mt++) {
#pragma unroll
        for (int nt = 0; nt < 8; nt++) {
            int row = m0 + wm + mt * 16 + g;
            int col = n0 + wn + nt * 8 + 2 * t4;
            C[(long)row * NF + col]       = acc[mt][nt][0];
            C[(long)row * NF + col + 1]   = acc[mt][nt][1];
            C[(long)(row + 8) * NF + col]     = acc[mt][nt][2];
            C[(long)(row + 8) * NF + col + 1] = acc[mt][nt][3];
        }
    }
}

// z=0: VQ0, z=1: DOT1
__global__ void __launch_bounds__(256) mm_vd() {
    if (blockIdx.z == 0)
        mm_core(g_x2, (long)BI * KP0, g_fdw2s, (long)NF * KP0, g_S, KP0);
    else
        mm_core(g_fpw2s, (long)NF * KP1, g_fdw22s, (long)NF * KP1, g_S + NN2, KP1);
}
// z = t: G_t
__global__ void __launch_bounds__(256) mm_g() {
    int t = blockIdx.z;
    mm_core(g_Cs2 + (long)t * NF * KP2, 9L * NF * KP2, g_fpw22s, (long)NF * KP2,
            g_G + (long)t * NN2, KP2);
}
__global__ void __launch_bounds__(256) mm_vq1() {
    mm_core(g_h12, (long)BI * KP1, g_fpw2s, (long)NF * KP1, g_S + 2L * NN2, KP1);
}

// ================= fused prep: Cs shift+split + norms + codebook splits + quantw =================
__global__ void prep_kernel(const float* __restrict__ cb_fdw, const float* __restrict__ cb_fpw,
                            const float* __restrict__ cb_fdw2, const float* __restrict__ cb_fpw2,
                            const float* __restrict__ dw1, const float* __restrict__ pw1,
                            const float* __restrict__ dw2, const float* __restrict__ pw2,
                            const float* __restrict__ cdw, const float* __restrict__ cpw,
                            const float* __restrict__ cdw2, const float* __restrict__ cpw2) {
    int b = blockIdx.x;
    if (b < 9 * NF) {
        // shifted cb_fdw2 -> tf32 splits, padded to KP2
        int k = b & (NF - 1), t = b >> 9;
        int ty = t / 3, tx = t - ty * 3;
        const float* src = cb_fdw2 + (long)k * D1;
        long base = ((long)t * NF + k) * KP2;
        const long pl = 9L * NF * KP2;
        for (int p = threadIdx.x; p < KP2; p += 256) {
            float v = 0.f;
            if (p < D2) {
                int py = p / H3c, px = p - py * H3c;
                v = src[(py + ty) * H2c + px + tx];
            }
            float h, l; split2(v, h, l);
            g_Cs2[base + p] = h; g_Cs2[pl + base + p] = l;
        }
        return;
    }
    b -= 9 * NF;
    if (b < 4 * NF) {
        // norms (exact fp32)
        int row = b & (NF - 1), which = b >> 9;
        const float* src; int D; float* dst;
        if (which == 0)      { src = cb_fdw;  D = D0; dst = g_nfdw;  }
        else if (which == 1) { src = cb_fpw;  D = D1; dst = g_nfpw;  }
        else if (which == 2) { src = cb_fdw2; D = D1; dst = g_nfdw2; }
        else                 { src = cb_fpw2; D = D2; dst = g_nfpw2; }
        const float* p = src + (long)row * D;
        float s = 0.f;
        for (int i = threadIdx.x; i < D; i += 256) { float v = p[i]; s += v * v; }
        __shared__ float sm[256];
        sm[threadIdx.x] = s; __syncthreads();
        for (int o = 128; o > 0; o >>= 1) {
            if (threadIdx.x < o) sm[threadIdx.x] += sm[threadIdx.x + o];
            __syncthreads();
        }
        if (threadIdx.x == 0) dst[row] = sm[0];
        return;
    }
    b -= 4 * NF;
    if (b < 4 * NF) {
        // codebook tf32 splits (padded)
        int row = b & (NF - 1), which = b >> 9;
        const float* src; int K, Kp; float* dst; long pl;
        if (which == 0)      { src = cb_fdw;  K = D0; Kp = KP0; dst = g_fdw2s;  pl = (long)NF * KP0; }
        else if (which == 1) { src = cb_fpw;  K = D1; Kp = KP1; dst = g_fpw2s;  pl = (long)NF * KP1; }
        else if (which == 2) { src = cb_fdw2; K = D1; Kp = KP1; dst = g_fdw22s; pl = (long)NF * KP1; }
        else                 { src = cb_fpw2; K = D2; Kp = KP2; dst = g_fpw22s; pl = (long)NF * KP2; }
        long base = (long)row * Kp;
        for (int p = threadIdx.x; p < Kp; p += 256) {
            float v = (p < K) ? src[(long)row * K + p] : 0.f;
            float h, l; split2(v, h, l);
            dst[base + p] = h; dst[pl + base + p] = l;
        }
        return;
    }
    // weight VQ (one block)
    int t = threadIdx.x;
    if (t < 32) {
        float w[9];
        for (int j = 0; j < 9; j++) w[j] = dw1[t * 9 + j];
        float bd = 3.4e38f; int bk = 0;
        for (int k = 0; k < 256; k++) {
            float d = 0.f;
            for (int j = 0; j < 9; j++) { float e = w[j] - cdw[k * 9 + j]; d += e * e; }
            if (d < bd) { bd = d; bk = k; }
        }
        for (int j = 0; j < 9; j++) g_qw1[t * 9 + j] = cdw[bk * 9 + j];
        for (int j = 0; j < 9; j++) w[j] = dw2[t * 9 + j];
        bd = 3.4e38f; bk = 0;
        for (int k = 0; k < 256; k++) {
            float d = 0.f;
            for (int j = 0; j < 9; j++) { float e = w[j] - cdw2[k * 9 + j]; d += e * e; }
            if (d < bd) { bd = d; bk = k; }
        }
        for (int j = 0; j < 9; j++) g_qw2[t * 9 + j] = cdw2[bk * 9 + j];
    }
    for (int c = t; c < OC; c += 256) {
        float w = pw1[c]; float bd = 3.4e38f; int bk = 0;
        for (int k = 0; k < 256; k++) { float e = w - cpw[k]; float d = e * e; if (d < bd) { bd = d; bk = k; } }
        g_qpw1[c] = cpw[bk];
        w = pw2[c]; bd = 3.4e38f; bk = 0;
        for (int k = 0; k < 256; k++) { float e = w - cpw2[k]; float d = e * e; if (d < bd) { bd = d; bk = k; } }
        g_qpw2[c] = cpw2[bk];
    }
}

// ---------------- split x ----------------
__global__ void split_x_kernel(const float* __restrict__ x) {
    int row = blockIdx.x;
    const long pl = (long)BI * KP0;
    long base = (long)row * KP0;
    for (int p = threadIdx.x; p < KP0; p += 256) {
        float v = x[(long)row * D0 + p];   // D0 == KP0
        float h, l; split2(v, h, l);
        g_x2[base + p] = h; g_x2[pl + base + p] = l;
    }
}

// ============ fused argmin(VQ0) + conv1 + lrelu + h1 tf32 split ============
__global__ void am0_conv1(const float* __restrict__ cb_fdw) {
    int v = blockIdx.x;
    int i = v & 31;
    __shared__ float sd[256]; __shared__ int si[256];
    __shared__ float w[9];
    __shared__ int s_idx;
    if (threadIdx.x < 9) w[threadIdx.x] = g_qw1[i * 9 + threadIdx.x];
    const float* Sr = g_S + (long)v * NF;
    float bd = 3.4e38f; int bk = 0;
    for (int k = threadIdx.x; k < NF; k += 256) {
        float d = g_nfdw[k] - 2.0f * Sr[k];
        if (d < bd) { bd = d; bk = k; }
    }
    sd[threadIdx.x] = bd; si[threadIdx.x] = bk; __syncthreads();
    for (int o = 128; o > 0; o >>= 1) {
        if (threadIdx.x < o) {
            float d2 = sd[threadIdx.x + o]; int k2 = si[threadIdx.x + o];
            if (d2 < sd[threadIdx.x] || (d2 == sd[threadIdx.x] && k2 < si[threadIdx.x])) {
                sd[threadIdx.x] = d2; si[threadIdx.x] = k2;
            }
        }
        __syncthreads();
    }
    if (threadIdx.x == 0) s_idx = si[0];
    __syncthreads();
    const float* src = cb_fdw + (long)s_idx * D0;
    const long pl = (long)BI * KP1;
    long base = (long)v * KP1;
    for (int p = threadIdx.x; p < KP1; p += 256) {
        float acc = 0.f;
        if (p < D1) {
            int py = p / H2c, px = p - py * H2c;
            const float* s0 = src + py * H0c + px;
            acc = s0[0] * w[0] + s0[1] * w[1] + s0[2] * w[2]
                + s0[H0c] * w[3] + s0[H0c + 1] * w[4] + s0[H0c + 2] * w[5]
                + s0[2 * H0c] * w[6] + s0[2 * H0c + 1] * w[7] + s0[2 * H0c + 2] * w[8];
            acc = (acc >= 0.f) ? acc : LEAK * acc;
        }
        float h, l; split2(acc, h, l);
        g_h12[base + p] = h; g_h12[pl + base + p] = l;
    }
}

// ============ fused argmin(VQ1) + idx2 scan ============
__global__ void am1_idx2() {
    int vbi = blockIdx.x;
    int b = vbi >> 5, i = vbi & 31;
    __shared__ float sd[256]; __shared__ int si[256];
    __shared__ int s_j;
    const float* S1r = g_S + 2L * NN2 + (long)vbi * NF;
    float bd = 3.4e38f; int bk = 0;
    for (int k = threadIdx.x; k < NF; k += 256) {
        float d = g_nfpw[k] - 2.0f * S1r[k];
        if (d < bd) { bd = d; bk = k; }
    }
    sd[threadIdx.x] = bd; si[threadIdx.x] = bk; __syncthreads();
    for (int o = 128; o > 0; o >>= 1) {
        if (threadIdx.x < o) {
            float d2 = sd[threadIdx.x + o]; int k2 = si[threadIdx.x + o];
            if (d2 < sd[threadIdx.x] || (d2 == sd[threadIdx.x] && k2 < si[threadIdx.x])) {
                sd[threadIdx.x] = d2; si[threadIdx.x] = k2;
            }
        }
        __syncthreads();
    }
    if (threadIdx.x == 0) s_j = si[0];
    __syncthreads();
    int j = s_j;
    __shared__ float dr[NF]; __shared__ float nn[NF];
    const float* Dr = g_S + NN2 + (long)j * NF;
    for (int k = threadIdx.x; k < NF; k += 256) { dr[k] = Dr[k]; nn[k] = g_nfdw2[k]; }
    __syncthreads();
    int warp = threadIdx.x >> 5, lane = threadIdx.x & 31;
    for (int o = warp; o < CH; o += 8) {
        float s = g_qpw1[o * 32 + i];
        float bd2 = 3.4e38f; int bk2 = 0;
        for (int k = lane; k < NF; k += 32) {
            float d = nn[k] - 2.0f * s * dr[k];
            if (d < bd2) { bd2 = d; bk2 = k; }
        }
        for (int off = 16; off > 0; off >>= 1) {
            float d2 = __shfl_down_sync(0xffffffffu, bd2, off);
            int k2 = __shfl_down_sync(0xffffffffu, bk2, off);
            if (d2 < bd2 || (d2 == bd2 && k2 < bk2)) { bd2 = d2; bk2 = k2; }
        }
        if (lane == 0) g_idx2[b * OC + o * 32 + i] = bk2;
    }
}

// ---------------- pair argmin over m per (k,o) ----------------
__global__ void __launch_bounds__(256) pair_kernel() {
    int k = blockIdx.x;
    __shared__ float gs[9][NF];
    __shared__ float nn[NF];
    __shared__ float ws[CH * 9];
    for (int t = 0; t < 9; t++)
        for (int m = threadIdx.x; m < NF; m += 256)
            gs[t][m] = g_G[((long)t * NF + k) * NF + m];
    for (int i = threadIdx.x; i < CH * 9; i += 256) ws[i] = g_qw2[i];
    for (int m = threadIdx.x; m < NF; m += 256) nn[m] = g_nfpw2[m];
    __syncthreads();
    int warp = threadIdx.x >> 5, lane = threadIdx.x & 31;
    for (int o = warp; o < CH; o += 8) {
        float wv[9];
#pragma unroll
        for (int t = 0; t < 9; t++) wv[t] = ws[o * 9 + t];
        float bd = 3.4e38f; int bk = 0;
        for (int m = lane; m < NF; m += 32) {
            float T = 0.f;
#pragma unroll
            for (int t = 0; t < 9; t++) T += wv[t] * gs[t][m];
            float d = nn[m] - 2.0f * T;
            if (d < bd) { bd = d; bk = m; }
        }
        for (int off = 16; off > 0; off >>= 1) {
            float d2 = __shfl_down_sync(0xffffffffu, bd, off);
            int k2 = __shfl_down_sync(0xffffffffu, bk, off);
            if (d2 < bd || (d2 == bd && k2 < bk)) { bd = d2; bk = k2; }
        }
        if (lane == 0) g_pair[k * CH + o] = bk;
    }
}

// ---------------- histogram ----------------
__global__ void cnt_kernel() {
    int bo = blockIdx.x;
    __shared__ int c[NF];
    for (int m = threadIdx.x; m < NF; m += 256) c[m] = 0;
    __syncthreads();
    if (threadIdx.x == 0) {
        int b = bo >> 5, o = bo & 31;
        for (int i = 0; i < 32; i++) {
            int k2 = g_idx2[b * OC + o * 32 + i];
            c[g_pair[k2 * CH + o]]++;
        }
    }
    __syncthreads();
    for (int m = threadIdx.x; m < NF; m += 256) g_cnt[(long)bo * NF + m] = c[m];
}

// ---------------- A[bg][m] = sum_o qpw2[g*32+o] * cnt[b][o][m] ----------------
__global__ void A_kernel() {
    int bg = blockIdx.x;
    int b = bg >> 5, g = bg & 31;
    __shared__ float w[32];
    if (threadIdx.x < 32) w[threadIdx.x] = g_qpw2[g * 32 + threadIdx.x];
    __syncthreads();
    for (int m = threadIdx.x; m < NF; m += 256) {
        float acc = 0.f;
#pragma unroll
        for (int o = 0; o < 32; o++)
            acc += w[o] * (float)g_cnt[((long)(b * 32 + o)) * NF + m];
        g_A[(long)bg * NF + m] = acc;
    }
}

// -------- out GEMM: partial C = A (512x512 chunk) * B (512x1936), split-K 2 (scalar) --------
__global__ void __launch_bounds__(256) sgemm_nn_split(
    const float* __restrict__ A, const float* __restrict__ B, float* __restrict__ C)
{
    const int N = D2, K = NF;
    int kb = blockIdx.z * 256, kend = kb + 256;
    C += (long)blockIdx.z * OSL;

    __shared__ float As[2][16][128];
    __shared__ float Bs[2][16][128];

    int tid = threadIdx.x;
    int m0 = blockIdx.y * 128, n0 = blockIdx.x * 128;
    int lr = tid >> 1, lc = (tid & 1) * 8;
    int krow = tid >> 4, nb_ = (tid & 15) * 8;
    int tx = tid & 15, ty = tid >> 4;

    const float* Ab = A + (long)(m0 + lr) * K;
    unsigned long long acc[8][4] = {};

    {
        float4 aL = *(const float4*)(Ab + kb + lc);
        float4 aH = *(const float4*)(Ab + kb + lc + 4);
        As[0][lc + 0][lr] = aL.x; As[0][lc + 1][lr] = aL.y; As[0][lc + 2][lr] = aL.z; As[0][lc + 3][lr] = aL.w;
        As[0][lc + 4][lr] = aH.x; As[0][lc + 5][lr] = aH.y; As[0][lc + 6][lr] = aH.z; As[0][lc + 7][lr] = aH.w;
        float4 bL = (n0 + nb_ < N) ? *(const float4*)(B + (long)(kb + krow) * N + n0 + nb_)
                                   : make_float4(0.f, 0.f, 0.f, 0.f);
        float4 bH = (n0 + nb_ + 4 < N) ? *(const float4*)(B + (long)(kb + krow) * N + n0 + nb_ + 4)
                                       : make_float4(0.f, 0.f, 0.f, 0.f);
        *(float4*)&Bs[0][krow][nb_] = bL;
        *(float4*)&Bs[0][krow][nb_ + 4] = bH;
    }
    __syncthreads();

    int buf = 0;
    for (int k0 = kb; k0 < kend; k0 += 16) {
        bool nxt = (k0 + 16) < kend;
        float4 naL, naH, nbL, nbH;
        if (nxt) {
            naL = *(const float4*)(Ab + k0 + 16 + lc);
            naH = *(const float4*)(Ab + k0 + 16 + lc + 4);
            nbL = (n0 + nb_ < N) ? *(const float4*)(B + (long)(k0 + 16 + krow) * N + n0 + nb_)
                                 : make_float4(0.f, 0.f, 0.f, 0.f);
            nbH = (n0 + nb_ + 4 < N) ? *(const float4*)(B + (long)(k0 + 16 + krow) * N + n0 + nb_ + 4)
                                     : make_float4(0.f, 0.f, 0.f, 0.f);
        }
#pragma unroll
        for (int kk = 0; kk < 16; kk++) {
            float4 a0 = *(const float4*)&As[buf][kk][ty * 4];
            float4 a1 = *(const float4*)&As[buf][kk][64 + ty * 4];
            ulonglong2 b01 = *(const ulonglong2*)&Bs[buf][kk][tx * 4];
            ulonglong2 b23 = *(const ulonglong2*)&Bs[buf][kk][64 + tx * 4];
            float ar[8] = { a0.x, a0.y, a0.z, a0.w, a1.x, a1.y, a1.z, a1.w };
#pragma unroll
            for (int i = 0; i < 8; i++) {
                unsigned long long ap; DUP2(ap, ar[i]);
                FMA2(acc[i][0], ap, b01.x); FMA2(acc[i][1], ap, b01.y);
                FMA2(acc[i][2], ap, b23.x); FMA2(acc[i][3], ap, b23.y);
            }
        }
        if (nxt) {
            int bN = buf ^ 1;
            As[bN][lc + 0][lr] = naL.x; As[bN][lc + 1][lr] = naL.y; As[bN][lc + 2][lr] = naL.z; As[bN][lc + 3][lr] = naL.w;
            As[bN][lc + 4][lr] = naH.x; As[bN][lc + 5][lr] = naH.y; As[bN][lc + 6][lr] = naH.z; As[bN][lc + 7][lr] = naH.w;
            *(float4*)&Bs[bN][krow][nb_] = nbL;
            *(float4*)&Bs[bN][krow][nb_ + 4] = nbH;
            __syncthreads();
            buf = bN;
        }
    }

#pragma unroll
    for (int i = 0; i < 8; i++) {
        int m = m0 + (i < 4 ? ty * 4 + i : 64 + ty * 4 + i - 4);
        float* Cr = C + (long)m * N;
#pragma unroll
        for (int jp = 0; jp < 4; jp++) {
            int n = n0 + (jp < 2 ? tx * 4 + jp * 2 : 64 + tx * 4 + (jp - 2) * 2);
            if (n < N) *(unsigned long long*)(Cr + n) = acc[i][jp];
        }
    }
}

// ---------------- BN + lrelu reduce of 2 out partials ----------------
__global__ void bn_reduce(const float* __restrict__ P, float* __restrict__ out,
                          const float* __restrict__ gamma, const float* __restrict__ beta,
                          const float* __restrict__ rmean, const float* __restrict__ rvar) {
    int m = blockIdx.x;
    int g = m & 31;
    float sc = rsqrtf(rvar[g] + BN_EPS) * gamma[g];
    float mu = rmean[g], bt = beta[g];
    const float* p0 = P + (long)m * D2;
    float* o = out + (long)m * D2;
    for (int n = threadIdx.x; n < D2; n += 256) {
        float v = p0[n] + p0[n + OSL];
        v = (v - mu) * sc + bt;
        o[n] = (v >= 0.f) ? v : LEAK * v;
    }
}

extern "C" void kernel_launch(void* const* d_in, const int* in_sizes, int n_in,
                              void* d_out, int out_size) {
    const float* x       = (const float*)d_in[0];
    const float* dw_w1   = (const float*)d_in[1];
    const float* pw_w1   = (const float*)d_in[2];
    const float* dw_w2   = (const float*)d_in[3];
    const float* pw_w2   = (const float*)d_in[4];
    const float* cb_dw   = (const float*)d_in[5];
    const float* cb_pw   = (const float*)d_in[6];
    const float* cb_dw2  = (const float*)d_in[7];
    const float* cb_pw2  = (const float*)d_in[8];
    const float* cb_fdw  = (const float*)d_in[9];
    const float* cb_fpw  = (const float*)d_in[10];
    const float* cb_fdw2 = (const float*)d_in[11];
    const float* cb_fpw2 = (const float*)d_in[12];
    const float* gamma   = (const float*)d_in[13];
    const float* beta    = (const float*)d_in[14];
    const float* rmean   = (const float*)d_in[15];
    const float* rvar    = (const float*)d_in[16];
    float* out = (float*)d_out;

    float *pA, *pOutP;
    cudaGetSymbolAddress((void**)&pA, g_A);
    cudaGetSymbolAddress((void**)&pOutP, g_OutP);

    // one-time host objects
    static cudaStream_t s1 = [] { cudaStream_t s; cudaStreamCreateWithFlags(&s, cudaStreamNonBlocking); return s; }();
    static cudaEvent_t eFork = [] { cudaEvent_t e; cudaEventCreateWithFlags(&e, cudaEventDisableTiming); return e; }();
    static cudaEvent_t ePrep = [] { cudaEvent_t e; cudaEventCreateWithFlags(&e, cudaEventDisableTiming); return e; }();
    static cudaEvent_t eVD   = [] { cudaEvent_t e; cudaEventCreateWithFlags(&e, cudaEventDisableTiming); return e; }();
    static cudaEvent_t ePair = [] { cudaEvent_t e; cudaEventCreateWithFlags(&e, cudaEventDisableTiming); return e; }();
    static bool attrs_ok = [] {
        cudaFuncSetAttribute(mm_vd,  cudaFuncAttributeMaxDynamicSharedMemorySize, MM_SMEM_BYTES);
        cudaFuncSetAttribute(mm_g,   cudaFuncAttributeMaxDynamicSharedMemorySize, MM_SMEM_BYTES);
        cudaFuncSetAttribute(mm_vq1, cudaFuncAttributeMaxDynamicSharedMemorySize, MM_SMEM_BYTES);
        return true;
    }();
    (void)attrs_ok;

    cudaEventRecord(eFork, 0);
    cudaStreamWaitEvent(s1, eFork, 0);

    // aux: prep (shifts + splits + norms + quantw)
    prep_kernel<<<9 * NF + 4 * NF + 4 * NF + 1, 256, 0, s1>>>(cb_fdw, cb_fpw, cb_fdw2, cb_fpw2,
                                                              dw_w1, pw_w1, dw_w2, pw_w2,
                                                              cb_dw, cb_pw, cb_dw2, cb_pw2);
    cudaEventRecord(ePrep, s1);

    // main: split x, then VQ0+DOT1 tensor GEMMs
    split_x_kernel<<<BI, 256>>>(x);
    cudaStreamWaitEvent(0, ePrep, 0);
    mm_vd<<<dim3(4, 4, 2), 256, MM_SMEM_BYTES>>>();
    cudaEventRecord(eVD, 0);

    // aux: G tensor GEMMs + pair (concurrent with main am0/VQ1/am1 chain)
    cudaStreamWaitEvent(s1, eVD, 0);
    mm_g<<<dim3(4, 4, 9), 256, MM_SMEM_BYTES, s1>>>();
    pair_kernel<<<NF, 256, 0, s1>>>();
    cudaEventRecord(ePair, s1);

    // main chain
    am0_conv1<<<BI, 256>>>(cb_fdw);
    mm_vq1<<<dim3(4, 4, 1), 256, MM_SMEM_BYTES>>>();
    am1_idx2<<<BI, 256>>>();
    cudaStreamWaitEvent(0, ePair, 0);
    cnt_kernel<<<B_ * CH, 256>>>();
    A_kernel<<<BI, 256>>>();
    sgemm_nn_split<<<dim3(16, 4, 2), 256>>>(pA, cb_fpw2, pOutP);
    bn_reduce<<<BI, 256>>>(pOutP, out, gamma, beta, rmean, rvar);
}

// round 11
// speedup vs baseline: 2.4218x; 2.4218x over previous
#include <cuda_runtime.h>

#define LEAK   0.1f
#define BN_EPS 1e-5f

// problem dims
#define B_   16
#define CH   32
#define H0c  48
#define H2c  46
#define H3c  44
#define D0   2304
#define D1   2116
#define D2   1936
#define NF   512
#define BI   512
#define OC   1024
#define BOC  16384
#define NN2  (NF * NF)
#define OSL  (512 * D2)

// ---------------- scratch ----------------
__device__ float g_Sp[8 * NN2];         // VQ0 partials [0:4) (reused by VQ1), DOT1 partials [4:8)
__device__ float g_G[9 * NN2];          // G (full-K, no splits)
__device__ float g_h1[BI * D1];
__device__ float g_Cs[9 * NF * D2];     // shifted cb_fdw2; later reused for out partials (2 slices)
__device__ float g_A[BI * NF];
__device__ int   g_cnt[B_ * CH * NF];
__device__ int   g_idx2[BOC];
__device__ int   g_pair[NF * CH];
__device__ float g_qw1[CH * 9];
__device__ float g_qw2[CH * 9];
__device__ float g_qpw1[OC];
__device__ float g_qpw2[OC];
__device__ float g_nfdw[NF];
__device__ float g_nfpw[NF];
__device__ float g_nfdw2[NF];
__device__ float g_nfpw2[NF];

// ---------------- packed fp32x2 helpers ----------------
#define FMA2(acc, a, b) asm("fma.rn.f32x2 %0, %1, %2, %0;" : "+l"(acc) : "l"(a), "l"(b))
#define DUP2(d, x) asm("mov.b64 %0, {%1, %1};" : "=l"(d) : "r"(__float_as_uint(x)))

// ================= fused prep: shift_prep + norms + quantw =================
__global__ void prep_kernel(const float* __restrict__ cb_fdw, const float* __restrict__ cb_fpw,
                            const float* __restrict__ cb_fdw2, const float* __restrict__ cb_fpw2,
                            const float* __restrict__ dw1, const float* __restrict__ pw1,
                            const float* __restrict__ dw2, const float* __restrict__ pw2,
                            const float* __restrict__ cdw, const float* __restrict__ cpw,
                            const float* __restrict__ cdw2, const float* __restrict__ cpw2) {
    int b = blockIdx.x;
    if (b < 9 * NF) {
        int k = b & (NF - 1), t = b >> 9;
        int ty = t / 3, tx = t - ty * 3;
        const float* src = cb_fdw2 + (long)k * D1;
        float* dst = g_Cs + ((long)t * NF + k) * D2;
        for (int p = threadIdx.x; p < D2; p += 256) {
            int py = p / H3c, px = p - py * H3c;
            dst[p] = src[(py + ty) * H2c + px + tx];
        }
        return;
    }
    b -= 9 * NF;
    if (b < 4 * NF) {
        int row = b & (NF - 1), which = b >> 9;
        const float* src; int D; float* dst;
        if (which == 0)      { src = cb_fdw;  D = D0; dst = g_nfdw;  }
        else if (which == 1) { src = cb_fpw;  D = D1; dst = g_nfpw;  }
        else if (which == 2) { src = cb_fdw2; D = D1; dst = g_nfdw2; }
        else                 { src = cb_fpw2; D = D2; dst = g_nfpw2; }
        const float* p = src + (long)row * D;
        float s = 0.f;
        for (int i = threadIdx.x; i < D; i += 256) { float v = p[i]; s += v * v; }
        __shared__ float sm[256];
        sm[threadIdx.x] = s; __syncthreads();
        for (int o = 128; o > 0; o >>= 1) {
            if (threadIdx.x < o) sm[threadIdx.x] += sm[threadIdx.x + o];
            __syncthreads();
        }
        if (threadIdx.x == 0) dst[row] = sm[0];
        return;
    }
    // weight VQ (one block)
    int t = threadIdx.x;
    if (t < 32) {
        float w[9];
        for (int j = 0; j < 9; j++) w[j] = dw1[t * 9 + j];
        float bd = 3.4e38f; int bk = 0;
        for (int k = 0; k < 256; k++) {
            float d = 0.f;
            for (int j = 0; j < 9; j++) { float e = w[j] - cdw[k * 9 + j]; d += e * e; }
            if (d < bd) { bd = d; bk = k; }
        }
        for (int j = 0; j < 9; j++) g_qw1[t * 9 + j] = cdw[bk * 9 + j];
        for (int j = 0; j < 9; j++) w[j] = dw2[t * 9 + j];
        bd = 3.4e38f; bk = 0;
        for (int k = 0; k < 256; k++) {
            float d = 0.f;
            for (int j = 0; j < 9; j++) { float e = w[j] - cdw2[k * 9 + j]; d += e * e; }
            if (d < bd) { bd = d; bk = k; }
        }
        for (int j = 0; j < 9; j++) g_qw2[t * 9 + j] = cdw2[bk * 9 + j];
    }
    for (int c = t; c < OC; c += 256) {
        float w = pw1[c]; float bd = 3.4e38f; int bk = 0;
        for (int k = 0; k < 256; k++) { float e = w - cpw[k]; float d = e * e; if (d < bd) { bd = d; bk = k; } }
        g_qpw1[c] = cpw[bk];
        w = pw2[c]; bd = 3.4e38f; bk = 0;
        for (int k = 0; k < 256; k++) { float e = w - cpw2[k]; float d = e * e; if (d < bd) { bd = d; bk = k; } }
        g_qpw2[c] = cpw2[bk];
    }
}

__device__ __forceinline__ float4 ld4_guard(const float* p, int k, int kend) {
    return (k < kend) ? *(const float4*)(p + k) : make_float4(0.f, 0.f, 0.f, 0.f);
}

// ================= NT GEMM core (R6 best): compact A, direct-u64 B, K-step 16 =================
__device__ __forceinline__ void nt_core(const float* __restrict__ A, const float* __restrict__ B,
                                        float* __restrict__ C, int ldk, int kb, int kend) {
    __shared__ float As[2][16][128];
    __shared__ float Bs[2][16][128];
    int tid = threadIdx.x;
    int m0 = blockIdx.y * 128, n0 = blockIdx.x * 128;
    int lr = tid >> 1, lc = (tid & 1) * 8;
    int tx = tid & 15, ty = tid >> 4;

    const float* Ab = A + (long)(m0 + lr) * ldk;
    const float* Bb = B + (long)(n0 + lr) * ldk;

    unsigned long long acc[8][4] = {};

    {
        float4 aL = ld4_guard(Ab, kb + lc, kend);
        float4 aH = ld4_guard(Ab, kb + lc + 4, kend);
        float4 bL = ld4_guard(Bb, kb + lc, kend);
        float4 bH = ld4_guard(Bb, kb + lc + 4, kend);
        As[0][lc + 0][lr] = aL.x; As[0][lc + 1][lr] = aL.y; As[0][lc + 2][lr] = aL.z; As[0][lc + 3][lr] = aL.w;
        As[0][lc + 4][lr] = aH.x; As[0][lc + 5][lr] = aH.y; As[0][lc + 6][lr] = aH.z; As[0][lc + 7][lr] = aH.w;
        Bs[0][lc + 0][lr] = bL.x; Bs[0][lc + 1][lr] = bL.y; Bs[0][lc + 2][lr] = bL.z; Bs[0][lc + 3][lr] = bL.w;
        Bs[0][lc + 4][lr] = bH.x; Bs[0][lc + 5][lr] = bH.y; Bs[0][lc + 6][lr] = bH.z; Bs[0][lc + 7][lr] = bH.w;
    }
    __syncthreads();

    int buf = 0;
    for (int k0 = kb; k0 < kend; k0 += 16) {
        bool nxt = (k0 + 16) < kend;
        float4 naL, naH, nbL, nbH;
        if (nxt) {
            naL = ld4_guard(Ab, k0 + 16 + lc, kend);
            naH = ld4_guard(Ab, k0 + 16 + lc + 4, kend);
            nbL = ld4_guard(Bb, k0 + 16 + lc, kend);
            nbH = ld4_guard(Bb, k0 + 16 + lc + 4, kend);
        }
#pragma unroll
        for (int kk = 0; kk < 16; kk++) {
            float4 a0 = *(const float4*)&As[buf][kk][ty * 4];
            float4 a1 = *(const float4*)&As[buf][kk][64 + ty * 4];
            ulonglong2 b01 = *(const ulonglong2*)&Bs[buf][kk][tx * 4];
            ulonglong2 b23 = *(const ulonglong2*)&Bs[buf][kk][64 + tx * 4];
            float ar[8] = { a0.x, a0.y, a0.z, a0.w, a1.x, a1.y, a1.z, a1.w };
#pragma unroll
            for (int i = 0; i < 8; i++) {
                unsigned long long ap; DUP2(ap, ar[i]);
                FMA2(acc[i][0], ap, b01.x); FMA2(acc[i][1], ap, b01.y);
                FMA2(acc[i][2], ap, b23.x); FMA2(acc[i][3], ap, b23.y);
            }
        }
        if (nxt) {
            int bN = buf ^ 1;
            As[bN][lc + 0][lr] = naL.x; As[bN][lc + 1][lr] = naL.y; As[bN][lc + 2][lr] = naL.z; As[bN][lc + 3][lr] = naL.w;
            As[bN][lc + 4][lr] = naH.x; As[bN][lc + 5][lr] = naH.y; As[bN][lc + 6][lr] = naH.z; As[bN][lc + 7][lr] = naH.w;
            Bs[bN][lc + 0][lr] = nbL.x; Bs[bN][lc + 1][lr] = nbL.y; Bs[bN][lc + 2][lr] = nbL.z; Bs[bN][lc + 3][lr] = nbL.w;
            Bs[bN][lc + 4][lr] = nbH.x; Bs[bN][lc + 5][lr] = nbH.y; Bs[bN][lc + 6][lr] = nbH.z; Bs[bN][lc + 7][lr] = nbH.w;
            __syncthreads();
            buf = bN;
        }
    }

#pragma unroll
    for (int i = 0; i < 8; i++) {
        int m = m0 + (i < 4 ? ty * 4 + i : 64 + ty * 4 + i - 4);
        float* Cr = C + (long)m * NF + n0;
        *(unsigned long long*)(Cr + tx * 4)          = acc[i][0];
        *(unsigned long long*)(Cr + tx * 4 + 2)      = acc[i][1];
        *(unsigned long long*)(Cr + 64 + tx * 4)     = acc[i][2];
        *(unsigned long long*)(Cr + 64 + tx * 4 + 2) = acc[i][3];
    }
}

// -------- VQ0: split-K 4 (z 0-3) --------
__global__ void __launch_bounds__(256) gemm_vq0(const float* __restrict__ x,
                                                const float* __restrict__ cbfdw) {
    int z = blockIdx.z;
    nt_core(x, cbfdw, g_Sp + (long)z * NN2, D0, z * 576, z * 576 + 576);
}

// -------- G: full-K, 9 z-slices --------
__global__ void __launch_bounds__(256) gemm_g(const float* __restrict__ cbfpw2) {
    int t = blockIdx.z;
    nt_core(g_Cs + (long)t * NF * D2, cbfpw2, g_G + (long)t * NN2, D2, 0, D2);
}

// -------- DOT1 (z 0-3) + VQ1 (z 4-7), both K=D1 split-4 --------
__global__ void __launch_bounds__(256) gemm_dot1_vq1(const float* __restrict__ cbfpw,
                                                     const float* __restrict__ cbfdw2) {
    int z = blockIdx.z;
    int s = z & 3;
    int kb = s * 532, kend = min(D1, kb + 532);
    if (z < 4)
        nt_core(cbfpw, cbfdw2, g_Sp + (long)(4 + s) * NN2, D1, kb, kend);
    else
        nt_core(g_h1, cbfpw, g_Sp + (long)s * NN2, D1, kb, kend);
}

// -------- out GEMM: partial C = A (512x512 chunk) * B (512x1936), split-K 2 --------
__global__ void __launch_bounds__(256) sgemm_nn_split(
    const float* __restrict__ A, const float* __restrict__ B, float* __restrict__ C)
{
    const int N = D2, K = NF;
    int kb = blockIdx.z * 256, kend = kb + 256;
    C += (long)blockIdx.z * OSL;

    __shared__ float As[2][16][128];
    __shared__ float Bs[2][16][128];

    int tid = threadIdx.x;
    int m0 = blockIdx.y * 128, n0 = blockIdx.x * 128;
    int lr = tid >> 1, lc = (tid & 1) * 8;
    int krow = tid >> 4, nb_ = (tid & 15) * 8;
    int tx = tid & 15, ty = tid >> 4;

    const float* Ab = A + (long)(m0 + lr) * K;
    unsigned long long acc[8][4] = {};

    {
        float4 aL = *(const float4*)(Ab + kb + lc);
        float4 aH = *(const float4*)(Ab + kb + lc + 4);
        As[0][lc + 0][lr] = aL.x; As[0][lc + 1][lr] = aL.y; As[0][lc + 2][lr] = aL.z; As[0][lc + 3][lr] = aL.w;
        As[0][lc + 4][lr] = aH.x; As[0][lc + 5][lr] = aH.y; As[0][lc + 6][lr] = aH.z; As[0][lc + 7][lr] = aH.w;
        float4 bL = (n0 + nb_ < N) ? *(const float4*)(B + (long)(kb + krow) * N + n0 + nb_)
                                   : make_float4(0.f, 0.f, 0.f, 0.f);
        float4 bH = (n0 + nb_ + 4 < N) ? *(const float4*)(B + (long)(kb + krow) * N + n0 + nb_ + 4)
                                       : make_float4(0.f, 0.f, 0.f, 0.f);
        *(float4*)&Bs[0][krow][nb_] = bL;
        *(float4*)&Bs[0][krow][nb_ + 4] = bH;
    }
    __syncthreads();

    int buf = 0;
    for (int k0 = kb; k0 < kend; k0 += 16) {
        bool nxt = (k0 + 16) < kend;
        float4 naL, naH, nbL, nbH;
        if (nxt) {
            naL = *(const float4*)(Ab + k0 + 16 + lc);
            naH = *(const float4*)(Ab + k0 + 16 + lc + 4);
            nbL = (n0 + nb_ < N) ? *(const float4*)(B + (long)(k0 + 16 + krow) * N + n0 + nb_)
                                 : make_float4(0.f, 0.f, 0.f, 0.f);
            nbH = (n0 + nb_ + 4 < N) ? *(const float4*)(B + (long)(k0 + 16 + krow) * N + n0 + nb_ + 4)
                                     : make_float4(0.f, 0.f, 0.f, 0.f);
        }
#pragma unroll
        for (int kk = 0; kk < 16; kk++) {
            float4 a0 = *(const float4*)&As[buf][kk][ty * 4];
            float4 a1 = *(const float4*)&As[buf][kk][64 + ty * 4];
            ulonglong2 b01 = *(const ulonglong2*)&Bs[buf][kk][tx * 4];
            ulonglong2 b23 = *(const ulonglong2*)&Bs[buf][kk][64 + tx * 4];
            float ar[8] = { a0.x, a0.y, a0.z, a0.w, a1.x, a1.y, a1.z, a1.w };
#pragma unroll
            for (int i = 0; i < 8; i++) {
                unsigned long long ap; DUP2(ap, ar[i]);
                FMA2(acc[i][0], ap, b01.x); FMA2(acc[i][1], ap, b01.y);
                FMA2(acc[i][2], ap, b23.x); FMA2(acc[i][3], ap, b23.y);
            }
        }
        if (nxt) {
            int bN = buf ^ 1;
            As[bN][lc + 0][lr] = naL.x; As[bN][lc + 1][lr] = naL.y; As[bN][lc + 2][lr] = naL.z; As[bN][lc + 3][lr] = naL.w;
            As[bN][lc + 4][lr] = naH.x; As[bN][lc + 5][lr] = naH.y; As[bN][lc + 6][lr] = naH.z; As[bN][lc + 7][lr] = naH.w;
            *(float4*)&Bs[bN][krow][nb_] = nbL;
            *(float4*)&Bs[bN][krow][nb_ + 4] = nbH;
            __syncthreads();
            buf = bN;
        }
    }

#pragma unroll
    for (int i = 0; i < 8; i++) {
        int m = m0 + (i < 4 ? ty * 4 + i : 64 + ty * 4 + i - 4);
        float* Cr = C + (long)m * N;
#pragma unroll
        for (int jp = 0; jp < 4; jp++) {
            int n = n0 + (jp < 2 ? tx * 4 + jp * 2 : 64 + tx * 4 + (jp - 2) * 2);
            if (n < N) *(unsigned long long*)(Cr + n) = acc[i][jp];
        }
    }
}

// ---------------- BN + lrelu reduce of 2 out partials ----------------
__global__ void bn_reduce(const float* __restrict__ P, float* __restrict__ out,
                          const float* __restrict__ gamma, const float* __restrict__ beta,
                          const float* __restrict__ rmean, const float* __restrict__ rvar) {
    int m = blockIdx.x;
    int g = m & 31;
    float sc = rsqrtf(rvar[g] + BN_EPS) * gamma[g];
    float mu = rmean[g], bt = beta[g];
    const float* p0 = P + (long)m * D2;
    float* o = out + (long)m * D2;
    for (int n = threadIdx.x; n < D2; n += 256) {
        float v = p0[n] + p0[n + OSL];
        v = (v - mu) * sc + bt;
        o[n] = (v >= 0.f) ? v : LEAK * v;
    }
}

// ============ fused argmin(VQ0) + conv1 + lrelu ============
__global__ void am0_conv1(const float* __restrict__ Sp, const float* __restrict__ cb_fdw) {
    int v = blockIdx.x;
    int i = v & 31;
    __shared__ float sd[256]; __shared__ int si[256];
    __shared__ float w[9];
    __shared__ int s_idx;
    if (threadIdx.x < 9) w[threadIdx.x] = g_qw1[i * 9 + threadIdx.x];
    float bd = 3.4e38f; int bk = 0;
    for (int k = threadIdx.x; k < NF; k += 256) {
        float s = 0.f;
#pragma unroll
        for (int sp = 0; sp < 4; sp++)
            s += Sp[((long)sp * NF + v) * NF + k];
        float d = g_nfdw[k] - 2.0f * s;
        if (d < bd) { bd = d; bk = k; }
    }
    sd[threadIdx.x] = bd; si[threadIdx.x] = bk; __syncthreads();
    for (int o = 128; o > 0; o >>= 1) {
        if (threadIdx.x < o) {
            float d2 = sd[threadIdx.x + o]; int k2 = si[threadIdx.x + o];
            if (d2 < sd[threadIdx.x] || (d2 == sd[threadIdx.x] && k2 < si[threadIdx.x])) {
                sd[threadIdx.x] = d2; si[threadIdx.x] = k2;
            }
        }
        __syncthreads();
    }
    if (threadIdx.x == 0) s_idx = si[0];
    __syncthreads();
    const float* src = cb_fdw + (long)s_idx * D0;
    for (int p = threadIdx.x; p < D1; p += 256) {
        int py = p / H2c, px = p - py * H2c;
        const float* s0 = src + py * H0c + px;
        float acc = s0[0] * w[0] + s0[1] * w[1] + s0[2] * w[2]
                  + s0[H0c] * w[3] + s0[H0c + 1] * w[4] + s0[H0c + 2] * w[5]
                  + s0[2 * H0c] * w[6] + s0[2 * H0c + 1] * w[7] + s0[2 * H0c + 2] * w[8];
        g_h1[(long)v * D1 + p] = (acc >= 0.f) ? acc : LEAK * acc;
    }
}

// ============ fused argmin(VQ1) + idx2 scan ============
__global__ void am1_idx2(const float* __restrict__ Vp, const float* __restrict__ DOT) {
    int vbi = blockIdx.x;
    int b = vbi >> 5, i = vbi & 31;
    __shared__ float sd[256]; __shared__ int si[256];
    __shared__ int s_j;
    float bd = 3.4e38f; int bk = 0;
    for (int k = threadIdx.x; k < NF; k += 256) {
        float s = 0.f;
#pragma unroll
        for (int sp = 0; sp < 4; sp++)
            s += Vp[((long)sp * NF + vbi) * NF + k];
        float d = g_nfpw[k] - 2.0f * s;
        if (d < bd) { bd = d; bk = k; }
    }
    sd[threadIdx.x] = bd; si[threadIdx.x] = bk; __syncthreads();
    for (int o = 128; o > 0; o >>= 1) {
        if (threadIdx.x < o) {
            float d2 = sd[threadIdx.x + o]; int k2 = si[threadIdx.x + o];
            if (d2 < sd[threadIdx.x] || (d2 == sd[threadIdx.x] && k2 < si[threadIdx.x])) {
                sd[threadIdx.x] = d2; si[threadIdx.x] = k2;
            }
        }
        __syncthreads();
    }
    if (threadIdx.x == 0) s_j = si[0];
    __syncthreads();
    int j = s_j;
    __shared__ float dr[NF]; __shared__ float nn[NF];
    for (int k = threadIdx.x; k < NF; k += 256) {
        float v = 0.f;
#pragma unroll
        for (int sp = 0; sp < 4; sp++)
            v += DOT[((long)sp * NF + j) * NF + k];
        dr[k] = v;
        nn[k] = g_nfdw2[k];
    }
    __syncthreads();
    int warp = threadIdx.x >> 5, lane = threadIdx.x & 31;
    for (int o = warp; o < CH; o += 8) {
        float s = g_qpw1[o * 32 + i];
        float bd2 = 3.4e38f; int bk2 = 0;
        for (int k = lane; k < NF; k += 32) {
            float d = nn[k] - 2.0f * s * dr[k];
            if (d < bd2) { bd2 = d; bk2 = k; }
        }
        for (int off = 16; off > 0; off >>= 1) {
            float d2 = __shfl_down_sync(0xffffffffu, bd2, off);
            int k2 = __shfl_down_sync(0xffffffffu, bk2, off);
            if (d2 < bd2 || (d2 == bd2 && k2 < bk2)) { bd2 = d2; bk2 = k2; }
        }
        if (lane == 0) g_idx2[b * OC + o * 32 + i] = bk2;
    }
}

// ---------------- pair argmin over m per (k,o), single G slice ----------------
__global__ void __launch_bounds__(256) pair_kernel() {
    int k = blockIdx.x;
    __shared__ float gs[9][NF];
    __shared__ float nn[NF];
    __shared__ float ws[CH * 9];
    for (int t = 0; t < 9; t++)
        for (int m = threadIdx.x; m < NF; m += 256)
            gs[t][m] = g_G[((long)t * NF + k) * NF + m];
    for (int i = threadIdx.x; i < CH * 9; i += 256) ws[i] = g_qw2[i];
    for (int m = threadIdx.x; m < NF; m += 256) nn[m] = g_nfpw2[m];
    __syncthreads();
    int warp = threadIdx.x >> 5, lane = threadIdx.x & 31;
    for (int o = warp; o < CH; o += 8) {
        float wv[9];
#pragma unroll
        for (int t = 0; t < 9; t++) wv[t] = ws[o * 9 + t];
        float bd = 3.4e38f; int bk = 0;
        for (int m = lane; m < NF; m += 32) {
            float T = 0.f;
#pragma unroll
            for (int t = 0; t < 9; t++) T += wv[t] * gs[t][m];
            float d = nn[m] - 2.0f * T;
            if (d < bd) { bd = d; bk = m; }
        }
        for (int off = 16; off > 0; off >>= 1) {
            float d2 = __shfl_down_sync(0xffffffffu, bd, off);
            int k2 = __shfl_down_sync(0xffffffffu, bk, off);
            if (d2 < bd || (d2 == bd && k2 < bk)) { bd = d2; bk = k2; }
        }
        if (lane == 0) g_pair[k * CH + o] = bk;
    }
}

// ---------------- histogram ----------------
__global__ void cnt_kernel() {
    int bo = blockIdx.x;
    __shared__ int c[NF];
    for (int m = threadIdx.x; m < NF; m += 256) c[m] = 0;
    __syncthreads();
    if (threadIdx.x == 0) {
        int b = bo >> 5, o = bo & 31;
        for (int i = 0; i < 32; i++) {
            int k2 = g_idx2[b * OC + o * 32 + i];
            c[g_pair[k2 * CH + o]]++;
        }
    }
    __syncthreads();
    for (int m = threadIdx.x; m < NF; m += 256) g_cnt[(long)bo * NF + m] = c[m];
}

// ---------------- A[bg][m] = sum_o qpw2[g*32+o] * cnt[b][o][m] ----------------
__global__ void A_kernel() {
    int bg = blockIdx.x;
    int b = bg >> 5, g = bg & 31;
    __shared__ float w[32];
    if (threadIdx.x < 32) w[threadIdx.x] = g_qpw2[g * 32 + threadIdx.x];
    __syncthreads();
    for (int m = threadIdx.x; m < NF; m += 256) {
        float acc = 0.f;
#pragma unroll
        for (int o = 0; o < 32; o++)
            acc += w[o] * (float)g_cnt[((long)(b * 32 + o)) * NF + m];
        g_A[(long)bg * NF + m] = acc;
    }
}

extern "C" void kernel_launch(void* const* d_in, const int* in_sizes, int n_in,
                              void* d_out, int out_size) {
    const float* x       = (const float*)d_in[0];
    const float* dw_w1   = (const float*)d_in[1];
    const float* pw_w1   = (const float*)d_in[2];
    const float* dw_w2   = (const float*)d_in[3];
    const float* pw_w2   = (const float*)d_in[4];
    const float* cb_dw   = (const float*)d_in[5];
    const float* cb_pw   = (const float*)d_in[6];
    const float* cb_dw2  = (const float*)d_in[7];
    const float* cb_pw2  = (const float*)d_in[8];
    const float* cb_fdw  = (const float*)d_in[9];
    const float* cb_fpw  = (const float*)d_in[10];
    const float* cb_fdw2 = (const float*)d_in[11];
    const float* cb_fpw2 = (const float*)d_in[12];
    const float* gamma   = (const float*)d_in[13];
    const float* beta    = (const float*)d_in[14];
    const float* rmean   = (const float*)d_in[15];
    const float* rvar    = (const float*)d_in[16];
    float* out = (float*)d_out;

    float *pSp, *pCs, *pA;
    cudaGetSymbolAddress((void**)&pSp, g_Sp);
    cudaGetSymbolAddress((void**)&pCs, g_Cs);
    cudaGetSymbolAddress((void**)&pA, g_A);

    static cudaStream_t s1 = [] { cudaStream_t s; cudaStreamCreateWithFlags(&s, cudaStreamNonBlocking); return s; }();
    static cudaEvent_t eFork = [] { cudaEvent_t e; cudaEventCreateWithFlags(&e, cudaEventDisableTiming); return e; }();
    static cudaEvent_t ePrep = [] { cudaEvent_t e; cudaEventCreateWithFlags(&e, cudaEventDisableTiming); return e; }();
    static cudaEvent_t ePair = [] { cudaEvent_t e; cudaEventCreateWithFlags(&e, cudaEventDisableTiming); return e; }();

    cudaEventRecord(eFork, 0);
    cudaStreamWaitEvent(s1, eFork, 0);

    // aux chain: prep -> G (full-K, 144 blocks) -> pair
    prep_kernel<<<9 * NF + 4 * NF + 1, 256, 0, s1>>>(cb_fdw, cb_fpw, cb_fdw2, cb_fpw2,
                                                     dw_w1, pw_w1, dw_w2, pw_w2,
                                                     cb_dw, cb_pw, cb_dw2, cb_pw2);
    cudaEventRecord(ePrep, s1);
    gemm_g<<<dim3(4, 4, 9), 256, 0, s1>>>(cb_fpw2);
    pair_kernel<<<NF, 256, 0, s1>>>();
    cudaEventRecord(ePair, s1);

    // main chain: VQ0 -> am0 -> (DOT1 + VQ1) -> am1 -> tail
    gemm_vq0<<<dim3(4, 4, 4), 256>>>(x, cb_fdw);
    cudaStreamWaitEvent(0, ePrep, 0);                        // norms + qw1
    am0_conv1<<<BI, 256>>>(pSp, cb_fdw);
    gemm_dot1_vq1<<<dim3(4, 4, 8), 256>>>(cb_fpw, cb_fdw2);
    am1_idx2<<<BI, 256>>>(pSp, pSp + 4L * NN2);
    cudaStreamWaitEvent(0, ePair, 0);
    cnt_kernel<<<B_ * CH, 256>>>();
    A_kernel<<<BI, 256>>>();
    sgemm_nn_split<<<dim3(16, 4, 2), 256>>>(pA, cb_fpw2, pCs);
    bn_reduce<<<BI, 256>>>(pCs, out, gamma, beta, rmean, rvar);
}